// round 6
// baseline (speedup 1.0000x reference)
#include <cuda_runtime.h>
#include <math.h>

#define ND 10000
#define NG 30000
#define HDIM 128
#define EDG 150000
#define EGD 150000
#define EGG 300000

// ---------------- scratch (device globals; no allocation) ----------------
__device__ float g_kqv_d[ND * 384];
__device__ float g_kqv_g[NG * 384];
__device__ float g_qt_d[ND * HDIM];
__device__ float g_qt_g0[NG * HDIM];
__device__ float g_qt_g2[NG * HDIM];
__device__ float g_agg_d[ND * HDIM];
__device__ float g_agg_g[NG * HDIM];
__device__ float g_x_d[ND * HDIM];
__device__ float g_x_g[NG * HDIM];
__device__ int g_cnt_g[NG + 1];
__device__ int g_off_g[NG + 1];
__device__ int g_cur_g[NG];
__device__ int g_list_g[EDG + EGG];
__device__ int g_cnt_d[ND + 1];
__device__ int g_off_d[ND + 1];
__device__ int g_cur_d[ND];
__device__ int g_list_d[EGD];

// ---------------- helpers ----------------
__device__ __forceinline__ float gelu_t(float x) {
    // jax.nn.gelu default: tanh approximation
    float u = 0.7978845608028654f * (x + 0.044715f * x * x * x);
    return 0.5f * x * (1.0f + tanhf(u));
}

__device__ __forceinline__ unsigned long long pack2(float lo, float hi) {
    unsigned long long r;
    asm("mov.b64 %0, {%1, %2};" : "=l"(r) : "f"(lo), "f"(hi));
    return r;
}
__device__ __forceinline__ void fma2(unsigned long long &acc, unsigned long long a,
                                     unsigned long long b) {
    asm("fma.rn.f32x2 %0, %1, %2, %0;" : "+l"(acc) : "l"(a), "l"(b));
}
__device__ __forceinline__ void unpack2(unsigned long long v, float &lo, float &hi) {
    asm("mov.b64 {%0, %1}, %2;" : "=f"(lo), "=f"(hi) : "l"(v));
}

// ---------------- CSR build ----------------
__global__ void hist_kernel(const int* __restrict__ dst, int E, int* cnt) {
    for (int i = blockIdx.x * blockDim.x + threadIdx.x; i < E; i += gridDim.x * blockDim.x)
        atomicAdd(&cnt[dst[i]], 1);
}

__global__ void scan_kernel(const int* __restrict__ cnt, int* __restrict__ off, int n) {
    __shared__ int part[1024];
    int t = threadIdx.x;
    int chunk = (n + 1023) / 1024;
    int b = t * chunk;
    int e = b + chunk;
    if (e > n) e = n;
    if (b > n) b = n;
    int s = 0;
    for (int i = b; i < e; i++) s += cnt[i];
    part[t] = s;
    __syncthreads();
    for (int d = 1; d < 1024; d <<= 1) {
        int v = 0;
        if (t >= d) v = part[t - d];
        __syncthreads();
        part[t] += v;
        __syncthreads();
    }
    int run = (t == 0) ? 0 : part[t - 1];
    for (int i = b; i < e; i++) { off[i] = run; run += cnt[i]; }
    if (t == 1023) off[n] = part[1023];
}

__global__ void fill_kernel(const int* __restrict__ src, const int* __restrict__ dst, int E,
                            const int* __restrict__ off, int* cur, int* list, int tbit) {
    for (int i = blockIdx.x * blockDim.x + threadIdx.x; i < E; i += gridDim.x * blockDim.x) {
        int d = dst[i];
        int pos = off[d] + atomicAdd(&cur[d], 1);
        list[pos] = (src[i] << 1) | tbit;
    }
}

// sort each node's segment (determinism of float accumulation order)
__global__ void sort_kernel(const int* __restrict__ off, int* list, int n) {
    int node = blockIdx.x * blockDim.x + threadIdx.x;
    if (node >= n) return;
    int b = off[node], e = off[node + 1];
    for (int i = b + 1; i < e; i++) {
        int v = list[i];
        int j = i - 1;
        while (j >= b && list[j] > v) { list[j + 1] = list[j]; j--; }
        list[j + 1] = v;
    }
}

// ---------------- GEMM: C[M,N] = f(A[M,128]) @ W[128,N] + bias (+ skip blend) ----------------
// MODE 0: C = A@W + b      (kqv projection)
// MODE 1: C = g*(gelu(A)@W + b) + (1-g)*xold,  g = sigmoid(skip)
template <int MODE>
__global__ __launch_bounds__(256) void gemm_k128(
    const float* __restrict__ A, const float* __restrict__ W,
    const float* __restrict__ bias, const float* __restrict__ xold,
    const float* __restrict__ skipp, float* __restrict__ C, int M, int N)
{
    __shared__ __align__(16) float As[16][64];
    __shared__ __align__(16) float Ws[16][64];
    const int tid = threadIdx.x;
    const int m0 = blockIdx.y * 64, n0 = blockIdx.x * 64;
    unsigned long long acc[4][2];
#pragma unroll
    for (int i = 0; i < 4; i++) { acc[i][0] = 0ull; acc[i][1] = 0ull; }

    const int ar = m0 + (tid >> 2);        // A row this thread loads
    const int ak = (tid & 3) << 2;         // k offset within 16-chunk
    const int wr = tid >> 4;               // W row within chunk
    const int wc = n0 + ((tid & 15) << 2); // W col
    const int ty = tid >> 4, tx = tid & 15;

    for (int k0 = 0; k0 < 128; k0 += 16) {
        float4 av = make_float4(0.f, 0.f, 0.f, 0.f);
        if (ar < M) av = *(const float4*)(A + (long)ar * 128 + k0 + ak);
        if (MODE == 1) {
            av.x = gelu_t(av.x); av.y = gelu_t(av.y);
            av.z = gelu_t(av.z); av.w = gelu_t(av.w);
        }
        As[ak + 0][tid >> 2] = av.x;
        As[ak + 1][tid >> 2] = av.y;
        As[ak + 2][tid >> 2] = av.z;
        As[ak + 3][tid >> 2] = av.w;
        float4 wv = *(const float4*)(W + (long)(k0 + wr) * N + wc);
        *(float4*)&Ws[wr][(tid & 15) << 2] = wv;
        __syncthreads();
#pragma unroll
        for (int kk = 0; kk < 16; kk++) {
            float4 a = *(const float4*)&As[kk][ty << 2];
            float4 b = *(const float4*)&Ws[kk][tx << 2];
            unsigned long long b01 = pack2(b.x, b.y), b23 = pack2(b.z, b.w);
            unsigned long long s;
            s = pack2(a.x, a.x); fma2(acc[0][0], s, b01); fma2(acc[0][1], s, b23);
            s = pack2(a.y, a.y); fma2(acc[1][0], s, b01); fma2(acc[1][1], s, b23);
            s = pack2(a.z, a.z); fma2(acc[2][0], s, b01); fma2(acc[2][1], s, b23);
            s = pack2(a.w, a.w); fma2(acc[3][0], s, b01); fma2(acc[3][1], s, b23);
        }
        __syncthreads();
    }

    const int mrow = m0 + (ty << 2);
    const int ncol = n0 + (tx << 2);
    float bv0 = bias[ncol], bv1 = bias[ncol + 1], bv2 = bias[ncol + 2], bv3 = bias[ncol + 3];
    float gate = 0.f, gate1 = 0.f;
    if (MODE == 1) {
        gate = 1.f / (1.f + __expf(-skipp[0]));
        gate1 = 1.f - gate;
    }
#pragma unroll
    for (int i = 0; i < 4; i++) {
        if (mrow + i < M) {
            float c0, c1, c2, c3;
            unpack2(acc[i][0], c0, c1);
            unpack2(acc[i][1], c2, c3);
            float o0 = c0 + bv0, o1 = c1 + bv1, o2 = c2 + bv2, o3 = c3 + bv3;
            float* Cp = C + (long)(mrow + i) * N + ncol;
            if (MODE == 0) {
                Cp[0] = o0; Cp[1] = o1; Cp[2] = o2; Cp[3] = o3;
            } else {
                const float* xo = xold + (long)(mrow + i) * N + ncol;
                Cp[0] = gate * o0 + gate1 * xo[0];
                Cp[1] = gate * o1 + gate1 * xo[1];
                Cp[2] = gate * o2 + gate1 * xo[2];
                Cp[3] = gate * o3 + gate1 * xo[3];
            }
        }
    }
}

// ---------------- q-tilde: qt[n,h,d] = (sum_f q[n,h,f]*arel[h,d,f]) * prel[h] * scale ----------
__global__ __launch_bounds__(128) void qt_kernel(
    const float* __restrict__ kqv, const float* __restrict__ arel,
    const float* __restrict__ prel, float scale,
    float* __restrict__ qt, int Nn)
{
    __shared__ float arelT[32][128]; // [f][h*32+d]
    __shared__ float qsh[128];
    const int t = threadIdx.x; // t = h*32+d
    for (int i = t; i < 4096; i += 128) {
        int h = i >> 10, rem = i & 1023;
        int d = rem >> 5, f = rem & 31;
        arelT[f][(h << 5) + d] = arel[i];
    }
    const int h = t >> 5;
    const float pr = prel[h] * scale;
    __syncthreads();
    for (int node = blockIdx.x; node < Nn; node += gridDim.x) {
        qsh[t] = kqv[(long)node * 384 + 128 + t]; // q block
        __syncthreads();
        float s = 0.f;
        const float* qh = &qsh[h << 5];
#pragma unroll
        for (int f = 0; f < 32; f++) s += qh[f] * arelT[f][t];
        qt[(long)node * 128 + t] = s * pr;
        __syncthreads();
    }
}

// ---------------- aggregation: warp per dst node, online softmax over incoming edges ----------
// list entry: (src<<1)|type_bit. type_bit selects (kqv table, q-tilde, mrel, accumulator).
// out[n,h,f] = ( sum_et sum_d S_et[h,d]*mrel_et[h,d,f] ) / lsum[h]
__global__ __launch_bounds__(256) void agg_kernel(
    const float* __restrict__ kqv0, const float* __restrict__ kqv1,
    const float* __restrict__ qt0t, const float* __restrict__ qt1t,
    const float* __restrict__ mrel0g, const float* __restrict__ mrel1g,
    const int* __restrict__ off, const int* __restrict__ list,
    float* __restrict__ agg, int Ndst, int two_types)
{
    __shared__ float mr0[4096];
    __shared__ float mr1[4096];
    __shared__ __align__(16) float Ssh[8][128];
    const int tid = threadIdx.x;
    for (int i = tid; i < 4096; i += 256) {
        mr0[i] = mrel0g[i];
        mr1[i] = mrel1g[i];
    }
    __syncthreads();
    const int warp = tid >> 5, lane = tid & 31;
    const int h = lane >> 3, f0 = (lane & 7) << 2;

    for (int node = blockIdx.x * 8 + warp; node < Ndst; node += gridDim.x * 8) {
        float4 q0 = ((const float4*)(qt0t + (long)node * 128))[lane];
        float4 q1 = make_float4(0.f, 0.f, 0.f, 0.f);
        if (two_types) q1 = ((const float4*)(qt1t + (long)node * 128))[lane];
        float m = -1e30f, lsum = 0.f;
        float4 S0 = make_float4(0.f, 0.f, 0.f, 0.f);
        float4 S1 = make_float4(0.f, 0.f, 0.f, 0.f);
        const int b = off[node], e = off[node + 1];
        for (int i = b; i < e; i++) {
            const int ent = list[i];
            const int tb = ent & 1;
            const float4* base = (const float4*)((tb ? kqv1 : kqv0) + (long)(ent >> 1) * 384);
            float4 k4 = base[lane];       // k block
            float4 qr = tb ? q1 : q0;
            float p = k4.x * qr.x + k4.y * qr.y + k4.z * qr.z + k4.w * qr.w;
            p += __shfl_xor_sync(0xffffffffu, p, 1);
            p += __shfl_xor_sync(0xffffffffu, p, 2);
            p += __shfl_xor_sync(0xffffffffu, p, 4);
            float mn = fmaxf(m, p);
            float c = __expf(m - mn);
            float ex = __expf(p - mn);
            m = mn;
            lsum = lsum * c + ex;
            float4 v4 = base[64 + lane];  // v block
            S0.x *= c; S0.y *= c; S0.z *= c; S0.w *= c;
            S1.x *= c; S1.y *= c; S1.z *= c; S1.w *= c;
            if (tb) { S1.x += ex * v4.x; S1.y += ex * v4.y; S1.z += ex * v4.z; S1.w += ex * v4.w; }
            else    { S0.x += ex * v4.x; S0.y += ex * v4.y; S0.z += ex * v4.z; S0.w += ex * v4.w; }
        }
        float inv = lsum > 0.f ? 1.f / lsum : 0.f;
        float4 o = make_float4(0.f, 0.f, 0.f, 0.f);
        ((float4*)Ssh[warp])[lane] = S0;
        __syncwarp();
        {
            const float* Sh = &Ssh[warp][h << 5];
            const float* Mm = &mr0[h << 10];
#pragma unroll
            for (int d = 0; d < 32; d++) {
                float s = Sh[d];
                const float* mp = Mm + (d << 5) + f0;
                o.x += s * mp[0]; o.y += s * mp[1]; o.z += s * mp[2]; o.w += s * mp[3];
            }
        }
        if (two_types) {
            __syncwarp();
            ((float4*)Ssh[warp])[lane] = S1;
            __syncwarp();
            const float* Sh = &Ssh[warp][h << 5];
            const float* Mm = &mr1[h << 10];
#pragma unroll
            for (int d = 0; d < 32; d++) {
                float s = Sh[d];
                const float* mp = Mm + (d << 5) + f0;
                o.x += s * mp[0]; o.y += s * mp[1]; o.z += s * mp[2]; o.w += s * mp[3];
            }
        }
        o.x *= inv; o.y *= inv; o.z *= inv; o.w *= inv;
        ((float4*)(agg + (long)node * 128))[lane] = o;
    }
}

// ---------------- host ----------------
extern "C" void kernel_launch(void* const* d_in, const int* in_sizes, int n_in,
                              void* d_out, int out_size) {
    const float* x_d    = (const float*)d_in[0];
    const float* x_g    = (const float*)d_in[1];
    const int*   src_dg = (const int*)d_in[2];
    const int*   dst_dg = (const int*)d_in[3];
    const int*   src_gd = (const int*)d_in[4];
    const int*   dst_gd = (const int*)d_in[5];
    const int*   src_gg = (const int*)d_in[6];
    const int*   dst_gg = (const int*)d_in[7];
    const float* Wkqv_d = (const float*)d_in[8];
    const float* bkqv_d = (const float*)d_in[9];
    const float* Wkqv_g = (const float*)d_in[10];
    const float* bkqv_g = (const float*)d_in[11];
    const float* Wout_d = (const float*)d_in[12];
    const float* bout_d = (const float*)d_in[13];
    const float* Wout_g = (const float*)d_in[14];
    const float* bout_g = (const float*)d_in[15];
    const float* skip_d = (const float*)d_in[16];
    const float* skip_g = (const float*)d_in[17];
    const float* arel   = (const float*)d_in[18];
    const float* mrel   = (const float*)d_in[19];
    const float* prel   = (const float*)d_in[20];

    float *kqv_d, *kqv_g, *qt_d, *qt_g0, *qt_g2, *agg_d, *agg_g, *xbuf_d, *xbuf_g;
    int *cnt_g, *off_g, *cur_g, *list_g, *cnt_d, *off_d, *cur_d, *list_d;
    cudaGetSymbolAddress((void**)&kqv_d, g_kqv_d);
    cudaGetSymbolAddress((void**)&kqv_g, g_kqv_g);
    cudaGetSymbolAddress((void**)&qt_d, g_qt_d);
    cudaGetSymbolAddress((void**)&qt_g0, g_qt_g0);
    cudaGetSymbolAddress((void**)&qt_g2, g_qt_g2);
    cudaGetSymbolAddress((void**)&agg_d, g_agg_d);
    cudaGetSymbolAddress((void**)&agg_g, g_agg_g);
    cudaGetSymbolAddress((void**)&xbuf_d, g_x_d);
    cudaGetSymbolAddress((void**)&xbuf_g, g_x_g);
    cudaGetSymbolAddress((void**)&cnt_g, g_cnt_g);
    cudaGetSymbolAddress((void**)&off_g, g_off_g);
    cudaGetSymbolAddress((void**)&cur_g, g_cur_g);
    cudaGetSymbolAddress((void**)&list_g, g_list_g);
    cudaGetSymbolAddress((void**)&cnt_d, g_cnt_d);
    cudaGetSymbolAddress((void**)&off_d, g_off_d);
    cudaGetSymbolAddress((void**)&cur_d, g_cur_d);
    cudaGetSymbolAddress((void**)&list_d, g_list_d);

    // ---- CSR build (edges identical across layers) ----
    cudaMemsetAsync(cnt_g, 0, sizeof(int) * NG);
    cudaMemsetAsync(cnt_d, 0, sizeof(int) * ND);
    hist_kernel<<<512, 256>>>(dst_dg, EDG, cnt_g);
    hist_kernel<<<512, 256>>>(dst_gg, EGG, cnt_g);
    hist_kernel<<<512, 256>>>(dst_gd, EGD, cnt_d);
    scan_kernel<<<1, 1024>>>(cnt_g, off_g, NG);
    scan_kernel<<<1, 1024>>>(cnt_d, off_d, ND);
    cudaMemsetAsync(cur_g, 0, sizeof(int) * NG);
    cudaMemsetAsync(cur_d, 0, sizeof(int) * ND);
    fill_kernel<<<512, 256>>>(src_dg, dst_dg, EDG, off_g, cur_g, list_g, 0);
    fill_kernel<<<512, 256>>>(src_gg, dst_gg, EGG, off_g, cur_g, list_g, 1);
    fill_kernel<<<512, 256>>>(src_gd, dst_gd, EGD, off_d, cur_d, list_d, 0);
    sort_kernel<<<(NG + 255) / 256, 256>>>(off_g, list_g, NG);
    sort_kernel<<<(ND + 255) / 256, 256>>>(off_d, list_d, ND);

    const float SCALE = 0.1767766952966369f; // 1/sqrt(32)
    const float* xd = x_d;
    const float* xg = x_g;
    for (int l = 0; l < 2; l++) {
        // fused K/Q/V projections
        gemm_k128<0><<<dim3(6, (ND + 63) / 64), 256>>>(
            xd, Wkqv_d + l * 128 * 384, bkqv_d + l * 384, nullptr, nullptr, kqv_d, ND, 384);
        gemm_k128<0><<<dim3(6, (NG + 63) / 64), 256>>>(
            xg, Wkqv_g + l * 128 * 384, bkqv_g + l * 384, nullptr, nullptr, kqv_g, NG, 384);
        // dst-side q-tilde per (dst node, edge type)
        qt_kernel<<<1024, 128>>>(kqv_g, arel + (l * 3 + 0) * 4096, prel + (l * 3 + 0) * 4,
                                 SCALE, qt_g0, NG);
        qt_kernel<<<1024, 128>>>(kqv_g, arel + (l * 3 + 2) * 4096, prel + (l * 3 + 2) * 4,
                                 SCALE, qt_g2, NG);
        qt_kernel<<<512, 128>>>(kqv_d, arel + (l * 3 + 1) * 4096, prel + (l * 3 + 1) * 4,
                                SCALE, qt_d, ND);
        // edge aggregation with joint segment softmax
        agg_kernel<<<(NG + 7) / 8, 256>>>(
            kqv_d, kqv_g, qt_g0, qt_g2,
            mrel + (l * 3 + 0) * 4096, mrel + (l * 3 + 2) * 4096,
            off_g, list_g, agg_g, NG, 1);
        agg_kernel<<<(ND + 7) / 8, 256>>>(
            kqv_g, kqv_g, qt_d, qt_d,
            mrel + (l * 3 + 1) * 4096, mrel + (l * 3 + 1) * 4096,
            off_d, list_d, agg_d, ND, 0);
        // output projection + gated skip
        float* od = (l == 1) ? (float*)d_out : xbuf_d;
        float* og = (l == 1) ? ((float*)d_out) + ND * HDIM : xbuf_g;
        gemm_k128<1><<<dim3(2, (ND + 63) / 64), 256>>>(
            agg_d, Wout_d + l * 128 * 128, bout_d + l * 128, xd, skip_d + l, od, ND, 128);
        gemm_k128<1><<<dim3(2, (NG + 63) / 64), 256>>>(
            agg_g, Wout_g + l * 128 * 128, bout_g + l * 128, xg, skip_g + l, og, NG, 128);
        xd = od;
        xg = og;
    }
}

// round 7
// speedup vs baseline: 1.1422x; 1.1422x over previous
#include <cuda_runtime.h>
#include <math.h>

#define ND 10000
#define NG 30000
#define HDIM 128
#define EDG 150000
#define EGD 150000
#define EGG 300000

typedef unsigned long long ull;

// ---------------- scratch (device globals; no allocation) ----------------
__device__ float g_kqv_d[ND * 384];
__device__ float g_kqv_g[NG * 384];
__device__ float g_qt_d[ND * HDIM];
__device__ float g_qt_g0[NG * HDIM];
__device__ float g_qt_g2[NG * HDIM];
__device__ float g_agg_d[ND * HDIM];
__device__ float g_agg_g[NG * HDIM];
__device__ float g_x_d[ND * HDIM];
__device__ float g_x_g[NG * HDIM];
__device__ int g_cnt_g[NG + 1];
__device__ int g_off_g[NG + 1];
__device__ int g_cur_g[NG];
__device__ int g_list_g[EDG + EGG];
__device__ int g_cnt_d[ND + 1];
__device__ int g_off_d[ND + 1];
__device__ int g_cur_d[ND];
__device__ int g_list_d[EGD];

// ---------------- helpers ----------------
__device__ __forceinline__ float gelu_t(float x) {
    float u = 0.7978845608028654f * (x + 0.044715f * x * x * x);
    return 0.5f * x * (1.0f + tanhf(u));
}
__device__ __forceinline__ ull pack2(float lo, float hi) {
    ull r;
    asm("mov.b64 %0, {%1, %2};" : "=l"(r) : "f"(lo), "f"(hi));
    return r;
}
__device__ __forceinline__ void fma2(ull &acc, ull a, ull b) {
    asm("fma.rn.f32x2 %0, %1, %2, %0;" : "+l"(acc) : "l"(a), "l"(b));
}
__device__ __forceinline__ void unpack2(ull v, float &lo, float &hi) {
    asm("mov.b64 {%0, %1}, %2;" : "=f"(lo), "=f"(hi) : "l"(v));
}

// ---------------- CSR build (merged) ----------------
__global__ void hist_all(const int* __restrict__ dst_dg, const int* __restrict__ dst_gg,
                         const int* __restrict__ dst_gd, int* cnt_g, int* cnt_d) {
    const int NTOT = EDG + EGG + EGD;
    for (int i = blockIdx.x * blockDim.x + threadIdx.x; i < NTOT; i += gridDim.x * blockDim.x) {
        if (i < EDG) atomicAdd(&cnt_g[dst_dg[i]], 1);
        else if (i < EDG + EGG) atomicAdd(&cnt_g[dst_gg[i - EDG]], 1);
        else atomicAdd(&cnt_d[dst_gd[i - EDG - EGG]], 1);
    }
}

// block 0 scans (cnt_g -> off_g, NG); block 1 scans (cnt_d -> off_d, ND)
__global__ void scan2_kernel(const int* __restrict__ cnt_g, int* __restrict__ off_g,
                             const int* __restrict__ cnt_d, int* __restrict__ off_d) {
    const int* cnt = blockIdx.x == 0 ? cnt_g : cnt_d;
    int* off = blockIdx.x == 0 ? off_g : off_d;
    int n = blockIdx.x == 0 ? NG : ND;
    __shared__ int part[1024];
    int t = threadIdx.x;
    int chunk = (n + 1023) / 1024;
    int b = t * chunk, e = b + chunk;
    if (e > n) e = n;
    if (b > n) b = n;
    int s = 0;
    for (int i = b; i < e; i++) s += cnt[i];
    part[t] = s;
    __syncthreads();
    for (int d = 1; d < 1024; d <<= 1) {
        int v = 0;
        if (t >= d) v = part[t - d];
        __syncthreads();
        part[t] += v;
        __syncthreads();
    }
    int run = (t == 0) ? 0 : part[t - 1];
    for (int i = b; i < e; i++) { off[i] = run; run += cnt[i]; }
    if (t == 1023) off[n] = part[1023];
}

__global__ void fill_all(const int* __restrict__ src_dg, const int* __restrict__ dst_dg,
                         const int* __restrict__ src_gg, const int* __restrict__ dst_gg,
                         const int* __restrict__ src_gd, const int* __restrict__ dst_gd,
                         const int* __restrict__ off_g, int* cur_g, int* list_g,
                         const int* __restrict__ off_d, int* cur_d, int* list_d) {
    const int NTOT = EDG + EGG + EGD;
    for (int i = blockIdx.x * blockDim.x + threadIdx.x; i < NTOT; i += gridDim.x * blockDim.x) {
        if (i < EDG) {
            int d = dst_dg[i];
            int pos = off_g[d] + atomicAdd(&cur_g[d], 1);
            list_g[pos] = (src_dg[i] << 1);
        } else if (i < EDG + EGG) {
            int j = i - EDG;
            int d = dst_gg[j];
            int pos = off_g[d] + atomicAdd(&cur_g[d], 1);
            list_g[pos] = (src_gg[j] << 1) | 1;
        } else {
            int j = i - EDG - EGG;
            int d = dst_gd[j];
            int pos = off_d[d] + atomicAdd(&cur_d[d], 1);
            list_d[pos] = (src_gd[j] << 1);
        }
    }
}

__global__ void sort_all(const int* __restrict__ off_g, int* list_g,
                         const int* __restrict__ off_d, int* list_d) {
    int node = blockIdx.x * blockDim.x + threadIdx.x;
    const int* off;
    int* list;
    if (node < NG) { off = off_g; list = list_g; }
    else if (node < NG + ND) { off = off_d; list = list_d; node -= NG; }
    else return;
    int b = off[node], e = off[node + 1];
    for (int i = b + 1; i < e; i++) {
        int v = list[i];
        int j = i - 1;
        while (j >= b && list[j] > v) { list[j + 1] = list[j]; j--; }
        list[j + 1] = v;
    }
}

// ---------------- GEMM 128x128 tile, K=128, 8x8 register blocking, f32x2 ----------------
// MODE 0: C = A@W + b
// MODE 1: C = g*(gelu(A)@W + b) + (1-g)*xold,  g = sigmoid(skip)
template <int MODE>
__global__ __launch_bounds__(256) void gemm_big(
    const float* __restrict__ A, const float* __restrict__ W,
    const float* __restrict__ bias, const float* __restrict__ xold,
    const float* __restrict__ skipp, float* __restrict__ C, int M, int N)
{
    __shared__ __align__(16) float As[2][8 * 136];
    __shared__ __align__(16) float Bs[2][8 * 128];
    const int tid = threadIdx.x;
    const int m0 = blockIdx.y * 128, n0 = blockIdx.x * 128;
    const int tx = tid & 15, ty = tid >> 4;

    // global load mapping
    const int lm = tid >> 1;             // A row within tile (0..127)
    const int lk = (tid & 1) << 2;       // A col sub-chunk (0 or 4)
    const int bk = tid >> 5;             // B row within chunk (0..7)
    const int bn = (tid & 31) << 2;      // B col (0..124)
    const int arow = m0 + lm;
    const bool avalid = (arow < M);
    const float* Aptr = A + (long)arow * 128 + lk;
    const float* Wptr = W + (long)bk * N + n0 + bn;

    ull acc[8][4];
#pragma unroll
    for (int i = 0; i < 8; i++)
#pragma unroll
        for (int j = 0; j < 4; j++) acc[i][j] = 0ull;

    float4 ag, bg;
    // prologue: load+store chunk 0
    ag = avalid ? *(const float4*)Aptr : make_float4(0.f, 0.f, 0.f, 0.f);
    if (MODE == 1) { ag.x = gelu_t(ag.x); ag.y = gelu_t(ag.y); ag.z = gelu_t(ag.z); ag.w = gelu_t(ag.w); }
    bg = *(const float4*)Wptr;
    As[0][(lk + 0) * 136 + lm] = ag.x;
    As[0][(lk + 1) * 136 + lm] = ag.y;
    As[0][(lk + 2) * 136 + lm] = ag.z;
    As[0][(lk + 3) * 136 + lm] = ag.w;
    *(float4*)&Bs[0][bk * 128 + bn] = bg;
    __syncthreads();

    for (int c = 0; c < 16; ++c) {
        const int buf = c & 1;
        if (c < 15) {
            const int k0 = (c + 1) * 8;
            ag = avalid ? *(const float4*)(Aptr + k0) : make_float4(0.f, 0.f, 0.f, 0.f);
            if (MODE == 1) { ag.x = gelu_t(ag.x); ag.y = gelu_t(ag.y); ag.z = gelu_t(ag.z); ag.w = gelu_t(ag.w); }
            bg = *(const float4*)(Wptr + (long)k0 * N);
        }
#pragma unroll
        for (int kk = 0; kk < 8; kk++) {
            const float* as = &As[buf][kk * 136];
            float4 a0 = *(const float4*)(as + (ty << 2));
            float4 a1 = *(const float4*)(as + 64 + (ty << 2));
            const float* bs = &Bs[buf][kk * 128];
            ulonglong2 b0 = *(const ulonglong2*)(bs + (tx << 2));
            ulonglong2 b1 = *(const ulonglong2*)(bs + 64 + (tx << 2));
            ull bb0 = b0.x, bb1 = b0.y, bb2 = b1.x, bb3 = b1.y;
            float av[8] = {a0.x, a0.y, a0.z, a0.w, a1.x, a1.y, a1.z, a1.w};
#pragma unroll
            for (int i = 0; i < 8; i++) {
                ull s = pack2(av[i], av[i]);
                fma2(acc[i][0], s, bb0);
                fma2(acc[i][1], s, bb1);
                fma2(acc[i][2], s, bb2);
                fma2(acc[i][3], s, bb3);
            }
        }
        if (c < 15) {
            __syncthreads();
            const int nb = buf ^ 1;
            As[nb][(lk + 0) * 136 + lm] = ag.x;
            As[nb][(lk + 1) * 136 + lm] = ag.y;
            As[nb][(lk + 2) * 136 + lm] = ag.z;
            As[nb][(lk + 3) * 136 + lm] = ag.w;
            *(float4*)&Bs[nb][bk * 128 + bn] = bg;
            __syncthreads();
        }
    }

    float gate = 0.f, gate1 = 0.f;
    if (MODE == 1) {
        gate = 1.f / (1.f + __expf(-skipp[0]));
        gate1 = 1.f - gate;
    }
#pragma unroll
    for (int i = 0; i < 8; i++) {
        const int row = m0 + ((i < 4) ? ((ty << 2) + i) : (64 + (ty << 2) + i - 4));
        if (row >= M) continue;
#pragma unroll
        for (int half = 0; half < 2; half++) {
            const int col = n0 + half * 64 + (tx << 2);
            float c0, c1, c2, c3;
            unpack2(acc[i][half * 2 + 0], c0, c1);
            unpack2(acc[i][half * 2 + 1], c2, c3);
            float o0 = c0 + bias[col + 0];
            float o1 = c1 + bias[col + 1];
            float o2 = c2 + bias[col + 2];
            float o3 = c3 + bias[col + 3];
            float* Cp = C + (long)row * N + col;
            if (MODE == 0) {
                Cp[0] = o0; Cp[1] = o1; Cp[2] = o2; Cp[3] = o3;
            } else {
                const float* xo = xold + (long)row * N + col;
                Cp[0] = gate * o0 + gate1 * xo[0];
                Cp[1] = gate * o1 + gate1 * xo[1];
                Cp[2] = gate * o2 + gate1 * xo[2];
                Cp[3] = gate * o3 + gate1 * xo[3];
            }
        }
    }
}

// ---------------- q-tilde: qt[n,h,d] = (sum_f q[n,h,f]*arel[h,d,f]) * prel[h] * scale ----------
// blockIdx.y selects edge-type config: 0 -> (g, et0), 1 -> (g, et2), 2 -> (d, et1)
__global__ __launch_bounds__(128) void qt_kernel(
    const float* __restrict__ kqv_g, const float* __restrict__ kqv_d,
    const float* __restrict__ arel_l, const float* __restrict__ prel_l, float scale,
    float* __restrict__ qt_g0, float* __restrict__ qt_g2, float* __restrict__ qt_d)
{
    const float* kqv;
    const float* arel;
    const float* prel;
    float* qt;
    int Nn;
    if (blockIdx.y == 0)      { kqv = kqv_g; arel = arel_l;            prel = prel_l;     qt = qt_g0; Nn = NG; }
    else if (blockIdx.y == 1) { kqv = kqv_g; arel = arel_l + 2 * 4096; prel = prel_l + 8; qt = qt_g2; Nn = NG; }
    else                      { kqv = kqv_d; arel = arel_l + 1 * 4096; prel = prel_l + 4; qt = qt_d;  Nn = ND; }

    __shared__ float arelT[32][128]; // [f][h*32+d]
    __shared__ float qsh[128];
    const int t = threadIdx.x; // t = h*32+d
    for (int i = t; i < 4096; i += 128) {
        int h = i >> 10, rem = i & 1023;
        int d = rem >> 5, f = rem & 31;
        arelT[f][(h << 5) + d] = arel[i];
    }
    const int h = t >> 5;
    const float pr = prel[h] * scale;
    __syncthreads();
    for (int node = blockIdx.x; node < Nn; node += gridDim.x) {
        qsh[t] = kqv[(long)node * 384 + 128 + t]; // q block
        __syncthreads();
        float s = 0.f;
        const float* qh = &qsh[h << 5];
#pragma unroll
        for (int f = 0; f < 32; f++) s += qh[f] * arelT[f][t];
        qt[(long)node * 128 + t] = s * pr;
        __syncthreads();
    }
}

// ---------------- aggregation: warp per dst node, online softmax over incoming edges ----------
__global__ __launch_bounds__(256) void agg_kernel(
    const float* __restrict__ kqv0, const float* __restrict__ kqv1,
    const float* __restrict__ qt0t, const float* __restrict__ qt1t,
    const float* __restrict__ mrel0g, const float* __restrict__ mrel1g,
    const int* __restrict__ off, const int* __restrict__ list,
    float* __restrict__ agg, int Ndst, int two_types)
{
    __shared__ float mr0[4096];
    __shared__ float mr1[4096];
    __shared__ __align__(16) float Ssh[8][128];
    const int tid = threadIdx.x;
    for (int i = tid; i < 4096; i += 256) {
        mr0[i] = mrel0g[i];
        mr1[i] = mrel1g[i];
    }
    __syncthreads();
    const int warp = tid >> 5, lane = tid & 31;
    const int h = lane >> 3, f0 = (lane & 7) << 2;

    for (int node = blockIdx.x * 8 + warp; node < Ndst; node += gridDim.x * 8) {
        float4 q0 = ((const float4*)(qt0t + (long)node * 128))[lane];
        float4 q1 = make_float4(0.f, 0.f, 0.f, 0.f);
        if (two_types) q1 = ((const float4*)(qt1t + (long)node * 128))[lane];
        float m = -1e30f, lsum = 0.f;
        float4 S0 = make_float4(0.f, 0.f, 0.f, 0.f);
        float4 S1 = make_float4(0.f, 0.f, 0.f, 0.f);
        const int b = off[node], e = off[node + 1];
        for (int i = b; i < e; i++) {
            const int ent = list[i];
            const int tb = ent & 1;
            const float4* base = (const float4*)((tb ? kqv1 : kqv0) + (long)(ent >> 1) * 384);
            float4 k4 = base[lane];       // k block
            float4 qr = tb ? q1 : q0;
            float p = k4.x * qr.x + k4.y * qr.y + k4.z * qr.z + k4.w * qr.w;
            p += __shfl_xor_sync(0xffffffffu, p, 1);
            p += __shfl_xor_sync(0xffffffffu, p, 2);
            p += __shfl_xor_sync(0xffffffffu, p, 4);
            float mn = fmaxf(m, p);
            float c = __expf(m - mn);
            float ex = __expf(p - mn);
            m = mn;
            lsum = lsum * c + ex;
            float4 v4 = base[64 + lane];  // v block
            S0.x *= c; S0.y *= c; S0.z *= c; S0.w *= c;
            S1.x *= c; S1.y *= c; S1.z *= c; S1.w *= c;
            if (tb) { S1.x += ex * v4.x; S1.y += ex * v4.y; S1.z += ex * v4.z; S1.w += ex * v4.w; }
            else    { S0.x += ex * v4.x; S0.y += ex * v4.y; S0.z += ex * v4.z; S0.w += ex * v4.w; }
        }
        float inv = lsum > 0.f ? 1.f / lsum : 0.f;
        float4 o = make_float4(0.f, 0.f, 0.f, 0.f);
        ((float4*)Ssh[warp])[lane] = S0;
        __syncwarp();
        {
            const float* Sh = &Ssh[warp][h << 5];
            const float* Mm = &mr0[h << 10];
#pragma unroll
            for (int d = 0; d < 32; d++) {
                float s = Sh[d];
                const float* mp = Mm + (d << 5) + f0;
                o.x += s * mp[0]; o.y += s * mp[1]; o.z += s * mp[2]; o.w += s * mp[3];
            }
        }
        if (two_types) {
            __syncwarp();
            ((float4*)Ssh[warp])[lane] = S1;
            __syncwarp();
            const float* Sh = &Ssh[warp][h << 5];
            const float* Mm = &mr1[h << 10];
#pragma unroll
            for (int d = 0; d < 32; d++) {
                float s = Sh[d];
                const float* mp = Mm + (d << 5) + f0;
                o.x += s * mp[0]; o.y += s * mp[1]; o.z += s * mp[2]; o.w += s * mp[3];
            }
        }
        o.x *= inv; o.y *= inv; o.z *= inv; o.w *= inv;
        ((float4*)(agg + (long)node * 128))[lane] = o;
    }
}

// ---------------- host ----------------
extern "C" void kernel_launch(void* const* d_in, const int* in_sizes, int n_in,
                              void* d_out, int out_size) {
    const float* x_d    = (const float*)d_in[0];
    const float* x_g    = (const float*)d_in[1];
    const int*   src_dg = (const int*)d_in[2];
    const int*   dst_dg = (const int*)d_in[3];
    const int*   src_gd = (const int*)d_in[4];
    const int*   dst_gd = (const int*)d_in[5];
    const int*   src_gg = (const int*)d_in[6];
    const int*   dst_gg = (const int*)d_in[7];
    const float* Wkqv_d = (const float*)d_in[8];
    const float* bkqv_d = (const float*)d_in[9];
    const float* Wkqv_g = (const float*)d_in[10];
    const float* bkqv_g = (const float*)d_in[11];
    const float* Wout_d = (const float*)d_in[12];
    const float* bout_d = (const float*)d_in[13];
    const float* Wout_g = (const float*)d_in[14];
    const float* bout_g = (const float*)d_in[15];
    const float* skip_d = (const float*)d_in[16];
    const float* skip_g = (const float*)d_in[17];
    const float* arel   = (const float*)d_in[18];
    const float* mrel   = (const float*)d_in[19];
    const float* prel   = (const float*)d_in[20];

    float *kqv_d, *kqv_g, *qt_d, *qt_g0, *qt_g2, *agg_d, *agg_g, *xbuf_d, *xbuf_g;
    int *cnt_g, *off_g, *cur_g, *list_g, *cnt_d, *off_d, *cur_d, *list_d;
    cudaGetSymbolAddress((void**)&kqv_d, g_kqv_d);
    cudaGetSymbolAddress((void**)&kqv_g, g_kqv_g);
    cudaGetSymbolAddress((void**)&qt_d, g_qt_d);
    cudaGetSymbolAddress((void**)&qt_g0, g_qt_g0);
    cudaGetSymbolAddress((void**)&qt_g2, g_qt_g2);
    cudaGetSymbolAddress((void**)&agg_d, g_agg_d);
    cudaGetSymbolAddress((void**)&agg_g, g_agg_g);
    cudaGetSymbolAddress((void**)&xbuf_d, g_x_d);
    cudaGetSymbolAddress((void**)&xbuf_g, g_x_g);
    cudaGetSymbolAddress((void**)&cnt_g, g_cnt_g);
    cudaGetSymbolAddress((void**)&off_g, g_off_g);
    cudaGetSymbolAddress((void**)&cur_g, g_cur_g);
    cudaGetSymbolAddress((void**)&list_g, g_list_g);
    cudaGetSymbolAddress((void**)&cnt_d, g_cnt_d);
    cudaGetSymbolAddress((void**)&off_d, g_off_d);
    cudaGetSymbolAddress((void**)&cur_d, g_cur_d);
    cudaGetSymbolAddress((void**)&list_d, g_list_d);

    // ---- CSR build (edges identical across layers) ----
    cudaMemsetAsync(cnt_g, 0, sizeof(int) * NG);
    cudaMemsetAsync(cnt_d, 0, sizeof(int) * ND);
    hist_all<<<512, 256>>>(dst_dg, dst_gg, dst_gd, cnt_g, cnt_d);
    scan2_kernel<<<2, 1024>>>(cnt_g, off_g, cnt_d, off_d);
    cudaMemsetAsync(cur_g, 0, sizeof(int) * NG);
    cudaMemsetAsync(cur_d, 0, sizeof(int) * ND);
    fill_all<<<512, 256>>>(src_dg, dst_dg, src_gg, dst_gg, src_gd, dst_gd,
                           off_g, cur_g, list_g, off_d, cur_d, list_d);
    sort_all<<<(NG + ND + 255) / 256, 256>>>(off_g, list_g, off_d, list_d);

    const float SCALE = 0.1767766952966369f; // 1/sqrt(32)
    const float* xd = x_d;
    const float* xg = x_g;
    for (int l = 0; l < 2; l++) {
        // fused K/Q/V projections
        gemm_big<0><<<dim3(3, (ND + 127) / 128), 256>>>(
            xd, Wkqv_d + l * 128 * 384, bkqv_d + l * 384, nullptr, nullptr, kqv_d, ND, 384);
        gemm_big<0><<<dim3(3, (NG + 127) / 128), 256>>>(
            xg, Wkqv_g + l * 128 * 384, bkqv_g + l * 384, nullptr, nullptr, kqv_g, NG, 384);
        // dst-side q-tilde per (dst node, edge type): y=0 (g,et0), y=1 (g,et2), y=2 (d,et1)
        qt_kernel<<<dim3(512, 3), 128>>>(kqv_g, kqv_d, arel + l * 3 * 4096, prel + l * 12,
                                         SCALE, qt_g0, qt_g2, qt_d);
        // edge aggregation with joint segment softmax
        agg_kernel<<<(NG + 7) / 8, 256>>>(
            kqv_d, kqv_g, qt_g0, qt_g2,
            mrel + (l * 3 + 0) * 4096, mrel + (l * 3 + 2) * 4096,
            off_g, list_g, agg_g, NG, 1);
        agg_kernel<<<(ND + 7) / 8, 256>>>(
            kqv_g, kqv_g, qt_d, qt_d,
            mrel + (l * 3 + 1) * 4096, mrel + (l * 3 + 1) * 4096,
            off_d, list_d, agg_d, ND, 0);
        // output projection + gated skip
        float* od = (l == 1) ? (float*)d_out : xbuf_d;
        float* og = (l == 1) ? ((float*)d_out) + ND * HDIM : xbuf_g;
        gemm_big<1><<<dim3(1, (ND + 127) / 128), 256>>>(
            agg_d, Wout_d + l * 128 * 128, bout_d + l * 128, xd, skip_d + l, od, ND, 128);
        gemm_big<1><<<dim3(1, (NG + 127) / 128), 256>>>(
            agg_g, Wout_g + l * 128 * 128, bout_g + l * 128, xg, skip_g + l, og, NG, 128);
        xd = od;
        xg = og;
    }
}